// round 8
// baseline (speedup 1.0000x reference)
#include <cuda_runtime.h>
#include <cuda_fp16.h>
#include <math.h>
#include <stdint.h>

#define NN 40000
#define NE 640000
#define H  128
#define ITERS 8

// GEMM smem byte offsets
#define WHI_B 0
#define WLO_B 34816
#define A_B   69632
#define SMEM_GEMM (69632 + 128 * 272)   // 104448 -> 2 CTAs/SM

// ---------------- device scratch ----------------
__device__ int   g_counts[NN];
__device__ int   g_rowptr[NN + 1];
__device__ int   g_cursor[NN];
__device__ int   g_col[NE];
__device__ int   g_bsums[320];
__device__ int   g_boffs[320];
__device__ float g_xp[NN * H];
__device__ uint2 g_st0[NN * 32];     // fp16 state rows (256 B)
__device__ uint2 g_st1[NN * 32];
__device__ uint2 g_dx[NN * 32];      // fp16 dense input (x)
__device__ uint2 g_dh[NN * 32];      // fp16 dense input (h0)
__device__ uint4 g_wp[4 * 4352];     // per slot: [hi 128x136][lo 128x136] fp16
__device__ int   g_is64;

// ---------------- PTX helpers ----------------
__device__ __forceinline__ uint32_t smem_u32(const void* p) {
    uint32_t a;
    asm("{ .reg .u64 t; cvta.to.shared.u64 t, %1; cvt.u32.u64 %0, t; }" : "=r"(a) : "l"(p));
    return a;
}
__device__ __forceinline__ void cpa16(uint32_t dst, const void* src) {
    asm volatile("cp.async.cg.shared.global [%0], [%1], 16;" :: "r"(dst), "l"(src));
}
__device__ __forceinline__ void cpa_commit() { asm volatile("cp.async.commit_group;"); }
__device__ __forceinline__ void cpa_wait0()  { asm volatile("cp.async.wait_group 0;"); }
__device__ __forceinline__ void ldsm4(uint32_t* r, uint32_t addr) {
    asm volatile("ldmatrix.sync.aligned.m8n8.x4.shared.b16 {%0,%1,%2,%3}, [%4];"
        : "=r"(r[0]), "=r"(r[1]), "=r"(r[2]), "=r"(r[3]) : "r"(addr));
}
__device__ __forceinline__ void mma16816(float* c, const uint32_t* a, const uint32_t* b) {
    asm volatile(
        "mma.sync.aligned.m16n8k16.row.col.f32.f16.f16.f32 "
        "{%0,%1,%2,%3}, {%4,%5,%6,%7}, {%8,%9}, {%0,%1,%2,%3};"
        : "+f"(c[0]), "+f"(c[1]), "+f"(c[2]), "+f"(c[3])
        : "r"(a[0]), "r"(a[1]), "r"(a[2]), "r"(a[3]), "r"(b[0]), "r"(b[1]));
}

// ---------------- CSR build ----------------
__global__ void zero_detect_kernel(const int* ei) {
    int i = blockIdx.x * blockDim.x + threadIdx.x;
    if (i < NN) g_counts[i] = 0;
    if (i == 0) {
        int any = 0;
        for (int k = 0; k < 128; k++) any |= ei[2 * k + 1];
        g_is64 = (any == 0) ? 1 : 0;
    }
}
__global__ void hist_kernel(const void* __restrict__ ei) {
    int e = blockIdx.x * blockDim.x + threadIdx.x;
    if (e >= NE) return;
    int d;
    if (g_is64) d = (int)((const long long*)ei)[NE + e];
    else        d = ((const int*)ei)[NE + e];
    atomicAdd(&g_counts[d], 1);
}
__global__ void bsum_kernel() {
    int i = blockIdx.x * 128 + threadIdx.x;
    int c = (i < NN) ? g_counts[i] : 0;
    for (int o = 16; o > 0; o >>= 1) c += __shfl_down_sync(~0u, c, o);
    __shared__ int ws[4];
    if ((threadIdx.x & 31) == 0) ws[threadIdx.x >> 5] = c;
    __syncthreads();
    if (threadIdx.x == 0) g_bsums[blockIdx.x] = ws[0] + ws[1] + ws[2] + ws[3];
}
__global__ void bscan_kernel() {
    __shared__ int sm[512];
    int t = threadIdx.x;
    int v = (t < 313) ? g_bsums[t] : 0;
    sm[t] = v;
    __syncthreads();
    for (int o = 1; o < 512; o <<= 1) {
        int u = (t >= o) ? sm[t - o] : 0;
        __syncthreads();
        sm[t] += u;
        __syncthreads();
    }
    if (t < 313) g_boffs[t] = sm[t] - v;
}
__global__ void rowptr_kernel() {
    int t = threadIdx.x;
    int i = blockIdx.x * 128 + t;
    int c = (i < NN) ? g_counts[i] : 0;
    int lane = t & 31, w = t >> 5;
    int v = c;
    for (int o = 1; o < 32; o <<= 1) {
        int u = __shfl_up_sync(~0u, v, o);
        if (lane >= o) v += u;
    }
    __shared__ int ws[4], wo[4];
    if (lane == 31) ws[w] = v;
    __syncthreads();
    if (t == 0) { int s = 0; for (int j = 0; j < 4; j++) { wo[j] = s; s += ws[j]; } }
    __syncthreads();
    int excl = v - c + wo[w] + g_boffs[blockIdx.x];
    if (i < NN) { g_rowptr[i] = excl; g_cursor[i] = excl; }
    if (blockIdx.x == 0 && t == 0) g_rowptr[NN] = NE;
}
__global__ void scatter_kernel(const void* __restrict__ ei) {
    int e = blockIdx.x * blockDim.x + threadIdx.x;
    if (e >= NE) return;
    int s, d;
    if (g_is64) {
        s = (int)((const long long*)ei)[e];
        d = (int)((const long long*)ei)[NE + e];
    } else {
        s = ((const int*)ei)[e];
        d = ((const int*)ei)[NE + e];
    }
    int p = atomicAdd(&g_cursor[d], 1);
    g_col[p] = s;
}

// ---------------- weight prep: fp32 -> fp16 hi/lo, [n][k] pad 136 ----------------
__global__ void prep_w_all(const float* __restrict__ w0, const float* __restrict__ w1,
                           const float* __restrict__ w2, const float* __restrict__ w3) {
    int slot = blockIdx.x >> 6;
    int idx  = (blockIdx.x & 63) * 256 + threadIdx.x;
    if (idx >= H * H) return;
    const float* w = (slot == 0) ? w0 : (slot == 1) ? w1 : (slot == 2) ? w2 : w3;
    int trans = slot & 1;
    int n = idx >> 7, k = idx & 127;
    float a = trans ? w[k * H + n] : w[n * H + k];
    __half hi = __float2half_rn(a);
    __half lo = __float2half_rn(a - __half2float(hi));
    __half* dst = (__half*)(g_wp + (size_t)slot * 4352);
    dst[n * 136 + k] = hi;
    dst[17408 + n * 136 + k] = lo;
}

// ---------------- split x -> fp16 ----------------
__global__ void split_x_kernel(const float4* __restrict__ src) {
    int i = blockIdx.x * blockDim.x + threadIdx.x;
    if (i >= NN * 32) return;
    float4 v = src[i];
    __half2 a = __floats2half2_rn(v.x, v.y);
    __half2 b = __floats2half2_rn(v.z, v.w);
    g_dx[i] = make_uint2(*(uint32_t*)&a, *(uint32_t*)&b);
}

// ---------------- fused (gather | dense-load) + tensor GEMM ----------------
// A = gather(st[src]) or dense fp16 rows; C = post(A @ W^T [+ XP]).
// DENSE 1: A via cp.async from Asrc rows.
// MODE 0: write xp fp32 + tanh -> fp16 dst (no ADD)
// MODE 1: ADD xp, tanh, write fp16
// MODE 3: ADD xp, tanh, write fp32
template <int DENSE, int MODE>
__global__ __launch_bounds__(256, 2)
void gemm_f(const uint2* __restrict__ Asrc, const uint4* __restrict__ W4,
            const float* __restrict__ XP, float* __restrict__ xpOut,
            void* __restrict__ dstOut) {
    extern __shared__ char smc[];
    const uint32_t sb = smem_u32(smc);
    const int tid = threadIdx.x, wid = tid >> 5, lane = tid & 31;
    const int rowBase = blockIdx.x * 128;

    // W load first — overlaps the gather phase
#pragma unroll
    for (int i = 0; i < 17; i++) {
        int f = tid + i * 256;
        cpa16(sb + f * 16, W4 + f);
    }
    cpa_commit();

    if (DENSE) {
#pragma unroll
        for (int i = 0; i < 8; i++) {
            int f = tid + i * 256;            // 0..2047 16B chunks
            int r = f >> 4, u = f & 15;
            int srow = rowBase + r; if (srow >= NN) srow = 0;  // dup row 0; epilogue masks
            cpa16(sb + A_B + r * 272 + u * 16,
                  (const char*)(Asrc + (size_t)srow * 32) + u * 16);
        }
        cpa_commit();
    } else {
        // gather: warp per node, 16 nodes per warp, unroll-4 edge loop
        const int* __restrict__ rp  = g_rowptr;
        const int* __restrict__ col = g_col;
#pragma unroll 1
        for (int t = 0; t < 16; t++) {
            const int j = wid * 16 + t;
            const int grow = rowBase + j;
            float a0 = 0.f, a1 = 0.f, a2 = 0.f, a3 = 0.f;
            if (grow < NN) {
                const int beg = rp[grow], end = rp[grow + 1];
                int p = beg;
                for (; p + 3 < end; p += 4) {
                    int s0 = col[p], s1 = col[p + 1], s2 = col[p + 2], s3 = col[p + 3];
                    uint2 v0 = __ldg(&Asrc[(size_t)s0 * 32 + lane]);
                    uint2 v1 = __ldg(&Asrc[(size_t)s1 * 32 + lane]);
                    uint2 v2 = __ldg(&Asrc[(size_t)s2 * 32 + lane]);
                    uint2 v3 = __ldg(&Asrc[(size_t)s3 * 32 + lane]);
                    float2 f0 = __half22float2(*(const __half2*)&v0.x);
                    float2 g0 = __half22float2(*(const __half2*)&v0.y);
                    float2 f1 = __half22float2(*(const __half2*)&v1.x);
                    float2 g1 = __half22float2(*(const __half2*)&v1.y);
                    float2 f2 = __half22float2(*(const __half2*)&v2.x);
                    float2 g2 = __half22float2(*(const __half2*)&v2.y);
                    float2 f3 = __half22float2(*(const __half2*)&v3.x);
                    float2 g3 = __half22float2(*(const __half2*)&v3.y);
                    a0 += (f0.x + f1.x) + (f2.x + f3.x);
                    a1 += (f0.y + f1.y) + (f2.y + f3.y);
                    a2 += (g0.x + g1.x) + (g2.x + g3.x);
                    a3 += (g0.y + g1.y) + (g2.y + g3.y);
                }
                for (; p < end; p++) {
                    uint2 v0 = __ldg(&Asrc[(size_t)col[p] * 32 + lane]);
                    float2 f0 = __half22float2(*(const __half2*)&v0.x);
                    float2 g0 = __half22float2(*(const __half2*)&v0.y);
                    a0 += f0.x; a1 += f0.y; a2 += g0.x; a3 += g0.y;
                }
            }
            __half2 p0 = __floats2half2_rn(a0, a1);
            __half2 p1 = __floats2half2_rn(a2, a3);
            *(uint2*)(smc + A_B + j * 272 + lane * 8) =
                make_uint2(*(uint32_t*)&p0, *(uint32_t*)&p1);
        }
    }
    cpa_wait0();
    __syncthreads();

    // fragment addressing
    const int qg = lane & 3, rg = lane >> 2;
    const int nq = wid & 1, mg = wid >> 1;
    const int lrow = lane & 15, khalf = lane >> 4;
    const uint32_t aoff0 = (uint32_t)(mg * 16 + lrow) * 272 + khalf * 16;
    const uint32_t aoff1 = (uint32_t)((mg + 4) * 16 + lrow) * 272 + khalf * 16;
    const int og = lane >> 3, lr = lane & 7;
    const uint32_t boff = (uint32_t)(nq * 64 + (og >> 1) * 8 + lr) * 272 + (og & 1) * 16;

    float acc[2][8][4];
#pragma unroll
    for (int m = 0; m < 2; m++)
#pragma unroll
        for (int nt = 0; nt < 8; nt++)
#pragma unroll
            for (int q = 0; q < 4; q++) acc[m][nt][q] = 0.f;

#pragma unroll
    for (int ks = 0; ks < 8; ks++) {
        const uint32_t kb = ks * 32;
        uint32_t a0[4], a1[4];
        ldsm4(a0, sb + A_B + aoff0 + kb);
        ldsm4(a1, sb + A_B + aoff1 + kb);
#pragma unroll
        for (int p = 0; p < 4; p++) {
            uint32_t bh[4], bl[4];
            ldsm4(bh, sb + WHI_B + boff + p * 4352 + kb);
            ldsm4(bl, sb + WLO_B + boff + p * 4352 + kb);
            mma16816(acc[0][2 * p],     a0, &bh[0]);
            mma16816(acc[0][2 * p],     a0, &bl[0]);
            mma16816(acc[0][2 * p + 1], a0, &bh[2]);
            mma16816(acc[0][2 * p + 1], a0, &bl[2]);
            mma16816(acc[1][2 * p],     a1, &bh[0]);
            mma16816(acc[1][2 * p],     a1, &bl[0]);
            mma16816(acc[1][2 * p + 1], a1, &bh[2]);
            mma16816(acc[1][2 * p + 1], a1, &bl[2]);
        }
    }

    // epilogue
#pragma unroll
    for (int m = 0; m < 2; m++) {
        const int t = mg + m * 4;
#pragma unroll
        for (int half = 0; half < 2; half++) {
            const int row = rowBase + t * 16 + rg + half * 8;
            if (row >= NN) continue;
#pragma unroll
            for (int nt = 0; nt < 8; nt++) {
                const int colj = nq * 64 + nt * 8 + qg * 2;
                float ox = acc[m][nt][half * 2], oy = acc[m][nt][half * 2 + 1];
                if (MODE != 0) {
                    float2 xv = *(const float2*)(XP + (size_t)row * H + colj);
                    ox += xv.x; oy += xv.y;
                }
                if (MODE == 0) {
                    *(float2*)(xpOut + (size_t)row * H + colj) = make_float2(ox, oy);
                    __half2 pp = __floats2half2_rn(tanhf(ox), tanhf(oy));
                    *(__half2*)((__half*)dstOut + (size_t)row * H + colj) = pp;
                } else if (MODE == 1) {
                    __half2 pp = __floats2half2_rn(tanhf(ox), tanhf(oy));
                    *(__half2*)((__half*)dstOut + (size_t)row * H + colj) = pp;
                } else {
                    *(float2*)((float*)dstOut + (size_t)row * H + colj) =
                        make_float2(tanhf(ox), tanhf(oy));
                }
            }
        }
    }
}

// ---------------- launcher ----------------
extern "C" void kernel_launch(void* const* d_in, const int* in_sizes, int n_in,
                              void* d_out, int out_size) {
    const void*  ei     = d_in[0];
    const float* x      = (const float*)d_in[1];
    const float* w_in0  = (const float*)d_in[2];
    const float* w_rec0 = (const float*)d_in[3];
    const float* w_in1  = (const float*)d_in[4];
    const float* w_rec1 = (const float*)d_in[5];
    float*       out    = (float*)d_out;

    void *pxp, *ps0, *ps1, *pdx, *pdh, *pwp;
    cudaGetSymbolAddress(&pxp, g_xp);
    cudaGetSymbolAddress(&ps0, g_st0);
    cudaGetSymbolAddress(&ps1, g_st1);
    cudaGetSymbolAddress(&pdx, g_dx);
    cudaGetSymbolAddress(&pdh, g_dh);
    cudaGetSymbolAddress(&pwp, g_wp);
    float* xp    = (float*)pxp;
    uint2* st[2] = { (uint2*)ps0, (uint2*)ps1 };
    uint2* dx    = (uint2*)pdx;
    uint2* dh    = (uint2*)pdh;
    uint4* wp    = (uint4*)pwp;

    cudaFuncSetAttribute(gemm_f<1, 0>, cudaFuncAttributeMaxDynamicSharedMemorySize, SMEM_GEMM);
    cudaFuncSetAttribute(gemm_f<0, 1>, cudaFuncAttributeMaxDynamicSharedMemorySize, SMEM_GEMM);
    cudaFuncSetAttribute(gemm_f<0, 3>, cudaFuncAttributeMaxDynamicSharedMemorySize, SMEM_GEMM);

    const int GB = (NN + 127) / 128;   // 313

    // ---- CSR build ----
    zero_detect_kernel<<<(NN + 255) / 256, 256>>>((const int*)ei);
    hist_kernel<<<(NE + 255) / 256, 256>>>(ei);
    bsum_kernel<<<GB, 128>>>();
    bscan_kernel<<<1, 512>>>();
    rowptr_kernel<<<GB, 128>>>();
    scatter_kernel<<<(NE + 255) / 256, 256>>>(ei);

    // ---- weight prep + x split ----
    prep_w_all<<<256, 256>>>(w_in0, w_rec0, w_in1, w_rec1);
    split_x_kernel<<<(NN * 32 + 255) / 256, 256>>>((const float4*)x);

    // ---- layer 0 ----
    gemm_f<1, 0><<<GB, 256, SMEM_GEMM>>>(dx, wp + 0 * 4352, nullptr, xp, st[0]);
    for (int it = 0; it < ITERS; it++) {
        void* dst = (it < ITERS - 1) ? (void*)st[(it + 1) & 1] : (void*)dh;
        gemm_f<0, 1><<<GB, 256, SMEM_GEMM>>>(st[it & 1], wp + 1 * 4352, xp, nullptr, dst);
    }

    // ---- layer 1 ----
    gemm_f<1, 0><<<GB, 256, SMEM_GEMM>>>(dh, wp + 2 * 4352, nullptr, xp, st[0]);
    for (int it = 0; it < ITERS; it++) {
        if (it < ITERS - 1)
            gemm_f<0, 1><<<GB, 256, SMEM_GEMM>>>(st[it & 1], wp + 3 * 4352, xp, nullptr, st[(it + 1) & 1]);
        else
            gemm_f<0, 3><<<GB, 256, SMEM_GEMM>>>(st[it & 1], wp + 3 * 4352, xp, nullptr, out);
    }
}

// round 9
// speedup vs baseline: 1.7034x; 1.7034x over previous
#include <cuda_runtime.h>
#include <cuda_fp16.h>
#include <math.h>
#include <stdint.h>

#define NN 40000
#define NE 640000
#define H  128
#define ITERS 8

#define TILE_R 144
#define MT 9
#define GBG 278                       // ceil(40000/144) -> single wave at 2 CTAs/SM
#define WHI_B 0
#define WLO_B 34816
#define A_B   69632
#define A_STRIDE 272                  // 256B row + 16B pad
#define SMEM_GEMM (A_B + TILE_R * A_STRIDE)   // 108800

// ---------------- device scratch ----------------
__device__ int   g_counts[NN];
__device__ int   g_rowptr[NN + 1];
__device__ int   g_cursor[NN];
__device__ int   g_col[NE];
__device__ int   g_bsums[320];
__device__ int   g_boffs[320];
__device__ uint2 g_xp16[NN * 32];    // fp16 xp rows
__device__ uint2 g_st0[NN * 32];     // fp16 state rows (256 B)
__device__ uint2 g_st1[NN * 32];
__device__ uint2 g_ag[NN * 32];      // fp16 aggr
__device__ uint2 g_dx[NN * 32];      // fp16 dense input (x)
__device__ uint2 g_dh[NN * 32];      // fp16 dense input (h0)
__device__ uint4 g_wp[4 * 4352];     // per slot: [hi 128x136][lo 128x136] fp16
__device__ int   g_is64;

// ---------------- PTX helpers ----------------
__device__ __forceinline__ uint32_t smem_u32(const void* p) {
    uint32_t a;
    asm("{ .reg .u64 t; cvta.to.shared.u64 t, %1; cvt.u32.u64 %0, t; }" : "=r"(a) : "l"(p));
    return a;
}
__device__ __forceinline__ void cpa16(uint32_t dst, const void* src) {
    asm volatile("cp.async.cg.shared.global [%0], [%1], 16;" :: "r"(dst), "l"(src));
}
__device__ __forceinline__ void cpa_commit() { asm volatile("cp.async.commit_group;"); }
__device__ __forceinline__ void cpa_wait0()  { asm volatile("cp.async.wait_group 0;"); }
__device__ __forceinline__ void ldsm4(uint32_t* r, uint32_t addr) {
    asm volatile("ldmatrix.sync.aligned.m8n8.x4.shared.b16 {%0,%1,%2,%3}, [%4];"
        : "=r"(r[0]), "=r"(r[1]), "=r"(r[2]), "=r"(r[3]) : "r"(addr));
}
__device__ __forceinline__ void mma16816(float* c, const uint32_t* a, const uint32_t* b) {
    asm volatile(
        "mma.sync.aligned.m16n8k16.row.col.f32.f16.f16.f32 "
        "{%0,%1,%2,%3}, {%4,%5,%6,%7}, {%8,%9}, {%0,%1,%2,%3};"
        : "+f"(c[0]), "+f"(c[1]), "+f"(c[2]), "+f"(c[3])
        : "r"(a[0]), "r"(a[1]), "r"(a[2]), "r"(a[3]), "r"(b[0]), "r"(b[1]));
}

// ---------------- fused prep: zero counts + detect + weight split + x split ------
__global__ void prep_all(const int* __restrict__ ei, const float4* __restrict__ x,
                         const float* __restrict__ w0, const float* __restrict__ w1,
                         const float* __restrict__ w2, const float* __restrict__ w3) {
    const int b = blockIdx.x;
    const int gi = b * 256 + threadIdx.x;
    if (gi < NN) g_counts[gi] = 0;
    if (gi == 0) {
        int any = 0;
        for (int k = 0; k < 128; k++) any |= ei[2 * k + 1];
        g_is64 = (any == 0) ? 1 : 0;
    }
    if (b < 256) {
        int slot = b >> 6;
        int idx  = (b & 63) * 256 + threadIdx.x;
        if (idx < H * H) {
            const float* w = (slot == 0) ? w0 : (slot == 1) ? w1 : (slot == 2) ? w2 : w3;
            int trans = slot & 1;
            int n = idx >> 7, k = idx & 127;
            float a = trans ? w[k * H + n] : w[n * H + k];
            __half hi = __float2half_rn(a);
            __half lo = __float2half_rn(a - __half2float(hi));
            __half* dst = (__half*)(g_wp + (size_t)slot * 4352);
            dst[n * 136 + k] = hi;
            dst[17408 + n * 136 + k] = lo;
        }
    } else {
        int i = gi - 65536;
        if (i < NN * 32) {
            float4 v = x[i];
            __half2 a = __floats2half2_rn(v.x, v.y);
            __half2 c = __floats2half2_rn(v.z, v.w);
            g_dx[i] = make_uint2(*(uint32_t*)&a, *(uint32_t*)&c);
        }
    }
}

// ---------------- CSR build ----------------
__global__ void hist_kernel(const void* __restrict__ ei) {
    int e = blockIdx.x * blockDim.x + threadIdx.x;
    if (e >= NE) return;
    int d;
    if (g_is64) d = (int)((const long long*)ei)[NE + e];
    else        d = ((const int*)ei)[NE + e];
    atomicAdd(&g_counts[d], 1);
}
__global__ void bsum_kernel() {
    int i = blockIdx.x * 128 + threadIdx.x;
    int c = (i < NN) ? g_counts[i] : 0;
    for (int o = 16; o > 0; o >>= 1) c += __shfl_down_sync(~0u, c, o);
    __shared__ int ws[4];
    if ((threadIdx.x & 31) == 0) ws[threadIdx.x >> 5] = c;
    __syncthreads();
    if (threadIdx.x == 0) g_bsums[blockIdx.x] = ws[0] + ws[1] + ws[2] + ws[3];
}
__global__ void bscan_kernel() {
    __shared__ int sm[512];
    int t = threadIdx.x;
    int v = (t < 313) ? g_bsums[t] : 0;
    sm[t] = v;
    __syncthreads();
    for (int o = 1; o < 512; o <<= 1) {
        int u = (t >= o) ? sm[t - o] : 0;
        __syncthreads();
        sm[t] += u;
        __syncthreads();
    }
    if (t < 313) g_boffs[t] = sm[t] - v;
}
__global__ void rowptr_kernel() {
    int t = threadIdx.x;
    int i = blockIdx.x * 128 + t;
    int c = (i < NN) ? g_counts[i] : 0;
    int lane = t & 31, w = t >> 5;
    int v = c;
    for (int o = 1; o < 32; o <<= 1) {
        int u = __shfl_up_sync(~0u, v, o);
        if (lane >= o) v += u;
    }
    __shared__ int ws[4], wo[4];
    if (lane == 31) ws[w] = v;
    __syncthreads();
    if (t == 0) { int s = 0; for (int j = 0; j < 4; j++) { wo[j] = s; s += ws[j]; } }
    __syncthreads();
    int excl = v - c + wo[w] + g_boffs[blockIdx.x];
    if (i < NN) { g_rowptr[i] = excl; g_cursor[i] = excl; }
    if (blockIdx.x == 0 && t == 0) g_rowptr[NN] = NE;
}
__global__ void scatter_kernel(const void* __restrict__ ei) {
    int e = blockIdx.x * blockDim.x + threadIdx.x;
    if (e >= NE) return;
    int s, d;
    if (g_is64) {
        s = (int)((const long long*)ei)[e];
        d = (int)((const long long*)ei)[NE + e];
    } else {
        s = ((const int*)ei)[e];
        d = ((const int*)ei)[NE + e];
    }
    int p = atomicAdd(&g_cursor[d], 1);
    g_col[p] = s;
}

// ---------------- CSR gather: fp16 state -> fp16 aggr (grid-stride, 1 wave) ------
__global__ __launch_bounds__(256) void gather_kernel(const uint2* __restrict__ st,
                                                     uint2* __restrict__ ag) {
    const int lane = threadIdx.x & 31;
    const int nwarp = (gridDim.x * blockDim.x) >> 5;
    for (int w = (blockIdx.x * blockDim.x + threadIdx.x) >> 5; w < NN; w += nwarp) {
        int beg = g_rowptr[w], end = g_rowptr[w + 1];
        float4 acc = make_float4(0.f, 0.f, 0.f, 0.f);
        int p = beg;
        for (; p + 1 < end; p += 2) {
            int s0 = g_col[p], s1 = g_col[p + 1];
            uint2 v0 = __ldg(&st[(size_t)s0 * 32 + lane]);
            uint2 v1 = __ldg(&st[(size_t)s1 * 32 + lane]);
            float2 a0 = __half22float2(*(const __half2*)&v0.x);
            float2 b0 = __half22float2(*(const __half2*)&v0.y);
            float2 a1 = __half22float2(*(const __half2*)&v1.x);
            float2 b1 = __half22float2(*(const __half2*)&v1.y);
            acc.x += a0.x + a1.x; acc.y += a0.y + a1.y;
            acc.z += b0.x + b1.x; acc.w += b0.y + b1.y;
        }
        if (p < end) {
            int s0 = g_col[p];
            uint2 v0 = __ldg(&st[(size_t)s0 * 32 + lane]);
            float2 a0 = __half22float2(*(const __half2*)&v0.x);
            float2 b0 = __half22float2(*(const __half2*)&v0.y);
            acc.x += a0.x; acc.y += a0.y; acc.z += b0.x; acc.w += b0.y;
        }
        __half2 h0v = __floats2half2_rn(acc.x, acc.y);
        __half2 h1v = __floats2half2_rn(acc.z, acc.w);
        ag[(size_t)w * 32 + lane] = make_uint2(*(uint32_t*)&h0v, *(uint32_t*)&h1v);
    }
}

// ---------------- tensor GEMM: C = post( A @ W^T [+ XP] ), single wave ------------
// MODE 0: write xp fp16 + tanh -> fp16 dst (no ADD); MODE 1: +xp, tanh, fp16;
// MODE 3: +xp, tanh, fp32
template <int MODE>
__global__ __launch_bounds__(256, 2)
void gemm_k(const uint4* __restrict__ Asrc, const uint4* __restrict__ W4,
            const __half* __restrict__ XP, __half* __restrict__ xpOut,
            void* __restrict__ dstOut) {
    extern __shared__ char smc[];
    const uint32_t sb = smem_u32(smc);
    const int tid = threadIdx.x, wid = tid >> 5, lane = tid & 31;
    const int rowBase = blockIdx.x * TILE_R;

#pragma unroll
    for (int i = 0; i < 17; i++) {
        int f = tid + i * 256;
        cpa16(sb + f * 16, W4 + f);
    }
#pragma unroll
    for (int i = 0; i < 9; i++) {
        int f = tid + i * 256;               // 0..2303
        int r = f >> 4, u = f & 15;
        int srow = rowBase + r; if (srow >= NN) srow = 0;
        cpa16(sb + A_B + r * A_STRIDE + u * 16, Asrc + (size_t)srow * 16 + u);
    }
    cpa_commit();
    cpa_wait0();
    __syncthreads();

    const int qg = lane & 3, rg = lane >> 2;
    const int nq = wid & 1, mg = wid >> 1;
    const int lrow = lane & 15, khalf = lane >> 4;
    const int og = lane >> 3, lr = lane & 7;
    const uint32_t boff = (uint32_t)(nq * 64 + (og >> 1) * 8 + lr) * 272 + (og & 1) * 16;

#pragma unroll
    for (int m = 0; m < 3; m++) {
        const int t = mg + m * 4;
        if (t >= MT) break;
        float acc[8][4];
#pragma unroll
        for (int nt = 0; nt < 8; nt++)
#pragma unroll
            for (int q = 0; q < 4; q++) acc[nt][q] = 0.f;

        const uint32_t aoffT = (uint32_t)(t * 16 + lrow) * A_STRIDE + khalf * 16;
#pragma unroll
        for (int ks = 0; ks < 8; ks++) {
            uint32_t a0[4];
            ldsm4(a0, sb + A_B + aoffT + ks * 32);
#pragma unroll
            for (int p = 0; p < 4; p++) {
                uint32_t bh[4], bl[4];
                ldsm4(bh, sb + WHI_B + boff + p * 4352 + ks * 32);
                ldsm4(bl, sb + WLO_B + boff + p * 4352 + ks * 32);
                mma16816(acc[2 * p],     a0, &bh[0]);
                mma16816(acc[2 * p],     a0, &bl[0]);
                mma16816(acc[2 * p + 1], a0, &bh[2]);
                mma16816(acc[2 * p + 1], a0, &bl[2]);
            }
        }

#pragma unroll
        for (int half = 0; half < 2; half++) {
            const int row = rowBase + t * 16 + rg + half * 8;
            if (row >= NN) continue;
#pragma unroll
            for (int nt = 0; nt < 8; nt++) {
                const int colj = nq * 64 + nt * 8 + qg * 2;
                float ox = acc[nt][half * 2], oy = acc[nt][half * 2 + 1];
                if (MODE != 0) {
                    float2 xv = __half22float2(*(const __half2*)(XP + (size_t)row * H + colj));
                    ox += xv.x; oy += xv.y;
                }
                if (MODE == 0) {
                    *(__half2*)(xpOut + (size_t)row * H + colj) = __floats2half2_rn(ox, oy);
                    *(__half2*)((__half*)dstOut + (size_t)row * H + colj) =
                        __floats2half2_rn(tanhf(ox), tanhf(oy));
                } else if (MODE == 1) {
                    *(__half2*)((__half*)dstOut + (size_t)row * H + colj) =
                        __floats2half2_rn(tanhf(ox), tanhf(oy));
                } else {
                    *(float2*)((float*)dstOut + (size_t)row * H + colj) =
                        make_float2(tanhf(ox), tanhf(oy));
                }
            }
        }
    }
}

// ---------------- launcher ----------------
extern "C" void kernel_launch(void* const* d_in, const int* in_sizes, int n_in,
                              void* d_out, int out_size) {
    const void*  ei     = d_in[0];
    const float* x      = (const float*)d_in[1];
    const float* w_in0  = (const float*)d_in[2];
    const float* w_rec0 = (const float*)d_in[3];
    const float* w_in1  = (const float*)d_in[4];
    const float* w_rec1 = (const float*)d_in[5];
    float*       out    = (float*)d_out;

    void *pxp, *ps0, *ps1, *pag, *pdx, *pdh, *pwp;
    cudaGetSymbolAddress(&pxp, g_xp16);
    cudaGetSymbolAddress(&ps0, g_st0);
    cudaGetSymbolAddress(&ps1, g_st1);
    cudaGetSymbolAddress(&pag, g_ag);
    cudaGetSymbolAddress(&pdx, g_dx);
    cudaGetSymbolAddress(&pdh, g_dh);
    cudaGetSymbolAddress(&pwp, g_wp);
    __half* xp   = (__half*)pxp;
    uint2* st[2] = { (uint2*)ps0, (uint2*)ps1 };
    uint2* ag    = (uint2*)pag;
    uint2* dx    = (uint2*)pdx;
    uint2* dh    = (uint2*)pdh;
    uint4* wp    = (uint4*)pwp;

    cudaFuncSetAttribute(gemm_k<0>, cudaFuncAttributeMaxDynamicSharedMemorySize, SMEM_GEMM);
    cudaFuncSetAttribute(gemm_k<1>, cudaFuncAttributeMaxDynamicSharedMemorySize, SMEM_GEMM);
    cudaFuncSetAttribute(gemm_k<3>, cudaFuncAttributeMaxDynamicSharedMemorySize, SMEM_GEMM);

    const int GB = (NN + 127) / 128;   // 313 (CSR helper grids)
    const int GGATHER = 1184;          // one wave of gather blocks

    prep_all<<<256 + (NN * 32 + 255) / 256, 256>>>((const int*)ei, (const float4*)x,
                                                   w_in0, w_rec0, w_in1, w_rec1);
    hist_kernel<<<(NE + 255) / 256, 256>>>(ei);
    bsum_kernel<<<GB, 128>>>();
    bscan_kernel<<<1, 512>>>();
    rowptr_kernel<<<GB, 128>>>();
    scatter_kernel<<<(NE + 255) / 256, 256>>>(ei);

    // ---- layer 0 ----
    gemm_k<0><<<GBG, 256, SMEM_GEMM>>>((const uint4*)dx, wp + 0 * 4352, nullptr, xp, st[0]);
    for (int it = 0; it < ITERS; it++) {
        gather_kernel<<<GGATHER, 256>>>(st[it & 1], ag);
        void* dst = (it < ITERS - 1) ? (void*)st[(it + 1) & 1] : (void*)dh;
        gemm_k<1><<<GBG, 256, SMEM_GEMM>>>((const uint4*)ag, wp + 1 * 4352, xp, nullptr, dst);
    }

    // ---- layer 1 ----
    gemm_k<0><<<GBG, 256, SMEM_GEMM>>>((const uint4*)dh, wp + 2 * 4352, nullptr, xp, st[0]);
    for (int it = 0; it < ITERS; it++) {
        gather_kernel<<<GGATHER, 256>>>(st[it & 1], ag);
        if (it < ITERS - 1)
            gemm_k<1><<<GBG, 256, SMEM_GEMM>>>((const uint4*)ag, wp + 3 * 4352, xp, nullptr, st[(it + 1) & 1]);
        else
            gemm_k<3><<<GBG, 256, SMEM_GEMM>>>((const uint4*)ag, wp + 3 * 4352, xp, nullptr, out);
    }
}